// round 1
// baseline (speedup 1.0000x reference)
#include <cuda_runtime.h>
#include <cuda_bf16.h>
#include <cstdint>

// Problem constants (match reference; runtime sizes still read from in_sizes)
#define NMAX 100000
#define HDIM 128

// ---------------- scratch (device globals; no allocations allowed) ----------
__device__ float g_h1  [(size_t)NMAX * HDIM];   // layer-1 output
__device__ float g_accP[(size_t)NMAX * HDIM];   // per-relation aggregation buffers
__device__ float g_accS[(size_t)NMAX * HDIM];
__device__ float g_deg [(size_t)4 * NMAX];      // [outP | inP | outS | inS] -> inverted in place

// ---------------- small utility kernels -------------------------------------
__global__ void zero_kernel(float4* __restrict__ p, int n4) {
    int i = blockIdx.x * blockDim.x + threadIdx.x;
    if (i < n4) p[i] = make_float4(0.f, 0.f, 0.f, 0.f);
}

__global__ void degree_kernel(const int* __restrict__ sP, const int* __restrict__ dP,
                              const int* __restrict__ sS, const int* __restrict__ dS,
                              float* __restrict__ deg, int E, int n) {
    int e = blockIdx.x * blockDim.x + threadIdx.x;
    if (e >= E) return;
    atomicAdd(&deg[sP[e]], 1.f);
    atomicAdd(&deg[n + dP[e]], 1.f);
    atomicAdd(&deg[2 * n + sS[e]], 1.f);
    atomicAdd(&deg[3 * n + dS[e]], 1.f);
}

__global__ void inv_kernel(float* __restrict__ deg, int n4) {
    int i = blockIdx.x * blockDim.x + threadIdx.x;
    if (i < n4) deg[i] = rsqrtf(fmaxf(deg[i], 1.f));
}

// ---------------- edge scatter: acc[dst] += coef * h[src] -------------------
// warp per edge: 32 lanes x float4 = 128 floats. blockIdx.y selects relation.
__global__ void edge_scatter(const float* __restrict__ h,
                             const int* __restrict__ srcP, const int* __restrict__ dstP,
                             const int* __restrict__ srcS, const int* __restrict__ dstS,
                             const float* __restrict__ inv,  // g_deg (inverted)
                             float* __restrict__ accP, float* __restrict__ accS,
                             int E, int n) {
    int rel = blockIdx.y;
    const int*   src  = rel ? srcS : srcP;
    const int*   dst  = rel ? dstS : dstP;
    const float* invo = inv + (rel ? 2 * (size_t)n : 0);
    const float* invi = inv + (rel ? 3 * (size_t)n : (size_t)n);
    float*       acc  = rel ? accS : accP;

    int warp = threadIdx.x >> 5;
    int lane = threadIdx.x & 31;
    int e = blockIdx.x * 8 + warp;
    if (e >= E) return;

    int s = __ldg(src + e);
    int d = __ldg(dst + e);
    float coef = __ldg(invo + s) * __ldg(invi + d);

    float4 v = __ldg((const float4*)(h + (size_t)s * HDIM) + lane);
    v.x *= coef; v.y *= coef; v.z *= coef; v.w *= coef;

    float* p = acc + (size_t)d * HDIM + lane * 4;
    asm volatile("red.global.add.v4.f32 [%0], {%1,%2,%3,%4};"
                 :: "l"(p), "f"(v.x), "f"(v.y), "f"(v.z), "f"(v.w) : "memory");
}

// ---------------- fused dual-GEMM + mean + bias + ReLU -----------------------
// out[m, :] = relu(0.5 * (A0[m,:]@W0 + A1[m,:]@W1 + b0 + b1))
// Classic 128x128 tile SGEMM, BK=16, 256 threads, 8x8 register tiles.
#define BM 128
#define BN 128
#define BK 16
__global__ __launch_bounds__(256) void gemm_fused(
    const float* __restrict__ A0, const float* __restrict__ A1,
    const float* __restrict__ W0, const float* __restrict__ W1,
    const float* __restrict__ b0, const float* __restrict__ b1,
    float* __restrict__ out, int M) {
    __align__(16) __shared__ float As[BK][BM];
    __align__(16) __shared__ float Bs[BK][BN];

    int tid = threadIdx.x;
    int block_row = blockIdx.x * BM;
    int tx = tid & 15;   // 16 threads across N (8 cols each)
    int ty = tid >> 4;   // 16 threads across M (8 rows each)

    float acc[8][8];
#pragma unroll
    for (int i = 0; i < 8; i++)
#pragma unroll
        for (int j = 0; j < 8; j++) acc[i][j] = 0.f;

#pragma unroll
    for (int seg = 0; seg < 2; ++seg) {
        const float* A = seg ? A1 : A0;
        const float* W = seg ? W1 : W0;
        for (int kb = 0; kb < HDIM; kb += BK) {
            // Load A tile: 128 rows x 16 k. 512 float4 / 256 threads = 2 each.
#pragma unroll
            for (int i = 0; i < 2; ++i) {
                int idx = tid + i * 256;
                int r = idx >> 2;        // row in tile
                int k4 = idx & 3;        // which float4 of the k-chunk
                int grow = block_row + r;
                float4 v = make_float4(0.f, 0.f, 0.f, 0.f);
                if (grow < M)
                    v = *(const float4*)(A + (size_t)grow * HDIM + kb + k4 * 4);
                As[k4 * 4 + 0][r] = v.x;
                As[k4 * 4 + 1][r] = v.y;
                As[k4 * 4 + 2][r] = v.z;
                As[k4 * 4 + 3][r] = v.w;
            }
            // Load W tile: 16 k-rows x 128 cols.
#pragma unroll
            for (int i = 0; i < 2; ++i) {
                int idx = tid + i * 256;
                int kr = idx >> 5;       // 0..15
                int c4 = idx & 31;       // float4 col
                float4 v = *(const float4*)(W + (size_t)(kb + kr) * HDIM + c4 * 4);
                *(float4*)&Bs[kr][c4 * 4] = v;
            }
            __syncthreads();
#pragma unroll
            for (int k = 0; k < BK; ++k) {
                float a[8], b[8];
                *(float4*)&a[0] = *(const float4*)&As[k][ty * 8];
                *(float4*)&a[4] = *(const float4*)&As[k][ty * 8 + 4];
                *(float4*)&b[0] = *(const float4*)&Bs[k][tx * 8];
                *(float4*)&b[4] = *(const float4*)&Bs[k][tx * 8 + 4];
#pragma unroll
                for (int i = 0; i < 8; i++)
#pragma unroll
                    for (int j = 0; j < 8; j++) acc[i][j] += a[i] * b[j];
            }
            __syncthreads();
        }
    }

    // epilogue: relu(0.5*(sum + b0 + b1))
    float bsum[8];
#pragma unroll
    for (int j = 0; j < 8; j++) {
        int col = tx * 8 + j;
        bsum[j] = __ldg(b0 + col) + __ldg(b1 + col);
    }
#pragma unroll
    for (int i = 0; i < 8; i++) {
        int grow = block_row + ty * 8 + i;
        if (grow >= M) break;
        float4 o0, o1;
        float v[8];
#pragma unroll
        for (int j = 0; j < 8; j++)
            v[j] = fmaxf(0.5f * (acc[i][j] + bsum[j]), 0.f);
        o0 = make_float4(v[0], v[1], v[2], v[3]);
        o1 = make_float4(v[4], v[5], v[6], v[7]);
        float* dst = out + (size_t)grow * HDIM + tx * 8;
        *(float4*)dst = o0;
        *(float4*)(dst + 4) = o1;
    }
}

// ---------------- pair classifier -------------------------------------------
// logits[p] = concat(z[ps], z[pd]) @ Wc + bc ; Wc [256,2] row-major
__global__ __launch_bounds__(256) void pair_logits(
    const float* __restrict__ z, const int* __restrict__ ps, const int* __restrict__ pd,
    const float* __restrict__ Wc, const float* __restrict__ bc,
    float* __restrict__ out, int P) {
    __shared__ float wcT[2][256];
    int tid = threadIdx.x;
    for (int i = tid; i < 256; i += 256) {
        wcT[0][i] = __ldg(Wc + i * 2 + 0);
        wcT[1][i] = __ldg(Wc + i * 2 + 1);
    }
    __syncthreads();

    int warp = tid >> 5, lane = tid & 31;
    int pair = blockIdx.x * 8 + warp;
    if (pair >= P) return;

    int a = __ldg(ps + pair);
    int b = __ldg(pd + pair);
    float4 va = __ldg((const float4*)(z + (size_t)a * HDIM) + lane);
    float4 vb = __ldg((const float4*)(z + (size_t)b * HDIM) + lane);
    int k = lane * 4;

    float4 w0a = *(const float4*)&wcT[0][k];
    float4 w1a = *(const float4*)&wcT[1][k];
    float4 w0b = *(const float4*)&wcT[0][k + 128];
    float4 w1b = *(const float4*)&wcT[1][k + 128];

    float c0 = va.x * w0a.x + va.y * w0a.y + va.z * w0a.z + va.w * w0a.w
             + vb.x * w0b.x + vb.y * w0b.y + vb.z * w0b.z + vb.w * w0b.w;
    float c1 = va.x * w1a.x + va.y * w1a.y + va.z * w1a.z + va.w * w1a.w
             + vb.x * w1b.x + vb.y * w1b.y + vb.z * w1b.z + vb.w * w1b.w;

#pragma unroll
    for (int o = 16; o; o >>= 1) {
        c0 += __shfl_down_sync(0xFFFFFFFFu, c0, o);
        c1 += __shfl_down_sync(0xFFFFFFFFu, c1, o);
    }
    if (lane == 0) {
        out[(size_t)pair * 2 + 0] = c0 + __ldg(bc + 0);
        out[(size_t)pair * 2 + 1] = c1 + __ldg(bc + 1);
    }
}

// ---------------- launch ------------------------------------------------------
extern "C" void kernel_launch(void* const* d_in, const int* in_sizes, int n_in,
                              void* d_out, int out_size) {
    const float* feat   = (const float*)d_in[0];
    const int*   srcP   = (const int*)d_in[1];
    const int*   dstP   = (const int*)d_in[2];
    const int*   srcS   = (const int*)d_in[3];
    const int*   dstS   = (const int*)d_in[4];
    const int*   pairS  = (const int*)d_in[5];
    const int*   pairD  = (const int*)d_in[6];
    const float* W0p    = (const float*)d_in[7];
    const float* b0p    = (const float*)d_in[8];
    const float* W0s    = (const float*)d_in[9];
    const float* b0s    = (const float*)d_in[10];
    const float* W1p    = (const float*)d_in[11];
    const float* b1p    = (const float*)d_in[12];
    const float* W1s    = (const float*)d_in[13];
    const float* W1sb   = (const float*)d_in[14];  // b1_sim
    const float* Wc     = (const float*)d_in[15];
    const float* bc     = (const float*)d_in[16];

    int N = in_sizes[0] / HDIM;
    int E = in_sizes[1];
    int P = in_sizes[5];

    float* out = (float*)d_out;
    float* z = out;                          // [N, H]
    float* logits = out + (size_t)N * HDIM;  // [P, 2]

    float *h1, *accP, *accS, *deg;
    cudaGetSymbolAddress((void**)&h1,   g_h1);
    cudaGetSymbolAddress((void**)&accP, g_accP);
    cudaGetSymbolAddress((void**)&accS, g_accS);
    cudaGetSymbolAddress((void**)&deg,  g_deg);

    // degrees -> inverse-sqrt norms
    {
        int n4 = (4 * N) / 4;
        zero_kernel<<<(n4 + 255) / 256, 256>>>((float4*)deg, n4);
        degree_kernel<<<(E + 255) / 256, 256>>>(srcP, dstP, srcS, dstS, deg, E, N);
        inv_kernel<<<(4 * N + 255) / 256, 256>>>(deg, 4 * N);
    }

    int acc4 = (N * HDIM) / 4;
    dim3 sgrid((E + 7) / 8, 2);
    int gemm_blocks = (N + BM - 1) / BM;

    // ---- layer 1 ----
    zero_kernel<<<(acc4 + 255) / 256, 256>>>((float4*)accP, acc4);
    zero_kernel<<<(acc4 + 255) / 256, 256>>>((float4*)accS, acc4);
    edge_scatter<<<sgrid, 256>>>(feat, srcP, dstP, srcS, dstS, deg, accP, accS, E, N);
    gemm_fused<<<gemm_blocks, 256>>>(accP, accS, W0p, W0s, b0p, b0s, h1, N);

    // ---- layer 2 ----
    zero_kernel<<<(acc4 + 255) / 256, 256>>>((float4*)accP, acc4);
    zero_kernel<<<(acc4 + 255) / 256, 256>>>((float4*)accS, acc4);
    edge_scatter<<<sgrid, 256>>>(h1, srcP, dstP, srcS, dstS, deg, accP, accS, E, N);
    gemm_fused<<<gemm_blocks, 256>>>(accP, accS, W1p, W1s, b1p, W1sb, z, N);

    // ---- pair classifier ----
    pair_logits<<<(P + 7) / 8, 256>>>(z, pairS, pairD, Wc, bc, logits, P);
}

// round 2
// speedup vs baseline: 1.7849x; 1.7849x over previous
#include <cuda_runtime.h>
#include <cuda_bf16.h>
#include <cstdint>

#define NMAX 100000
#define EMAX 1600000
#define HDIM 128
#define NBMAX 128   // max scan blocks (ceil(100000/1024)=98)

// ---------------- scratch (device globals; no allocations allowed) ----------
__device__ float g_h1  [(size_t)NMAX * HDIM];
__device__ float g_accP[(size_t)NMAX * HDIM];
__device__ float g_accS[(size_t)NMAX * HDIM];
__device__ float g_deg [(size_t)4 * NMAX];        // [outP | inP | outS | inS] -> inverted
__device__ int2  g_perm  [(size_t)2 * EMAX];      // dst-sorted (src, coef-bits), per relation
__device__ int   g_rowptr[(size_t)2 * NMAX];
__device__ int   g_cursor[(size_t)2 * NMAX];
__device__ int   g_hist  [(size_t)2 * NMAX];
__device__ int   g_bsum  [2 * NBMAX];
__device__ int   g_boff  [2 * NBMAX];

// ---------------- utility ----------------------------------------------------
__global__ void zero_f4(float4* __restrict__ p, int n4) {
    int i = blockIdx.x * blockDim.x + threadIdx.x;
    if (i < n4) p[i] = make_float4(0.f, 0.f, 0.f, 0.f);
}
__global__ void zero_i(int* __restrict__ p, int n) {
    int i = blockIdx.x * blockDim.x + threadIdx.x;
    if (i < n) p[i] = 0;
}

__global__ void degree_kernel(const int* __restrict__ sP, const int* __restrict__ dP,
                              const int* __restrict__ sS, const int* __restrict__ dS,
                              float* __restrict__ deg, int* __restrict__ hist,
                              int E, int n) {
    int e = blockIdx.x * blockDim.x + threadIdx.x;
    if (e >= E) return;
    int dp = dP[e], ds = dS[e];
    atomicAdd(&deg[sP[e]], 1.f);
    atomicAdd(&deg[n + dp], 1.f);
    atomicAdd(&deg[2 * n + sS[e]], 1.f);
    atomicAdd(&deg[3 * n + ds], 1.f);
    atomicAdd(&hist[dp], 1);
    atomicAdd(&hist[n + ds], 1);
}

__global__ void inv_kernel(float* __restrict__ deg, int n4) {
    int i = blockIdx.x * blockDim.x + threadIdx.x;
    if (i < n4) deg[i] = rsqrtf(fmaxf(deg[i], 1.f));
}

// ---------------- exclusive scan (2-level) -----------------------------------
__global__ __launch_bounds__(1024) void scan_partial(
    const int* __restrict__ hist, int* __restrict__ rowptr,
    int* __restrict__ bsum, int n) {
    __shared__ int sh[1024];
    int rel = blockIdx.y;
    int tid = threadIdx.x;
    int i = blockIdx.x * 1024 + tid;
    int v = (i < n) ? hist[(size_t)rel * n + i] : 0;
    sh[tid] = v;
    __syncthreads();
#pragma unroll
    for (int o = 1; o < 1024; o <<= 1) {
        int t = (tid >= o) ? sh[tid - o] : 0;
        __syncthreads();
        sh[tid] += t;
        __syncthreads();
    }
    if (i < n) rowptr[(size_t)rel * n + i] = sh[tid] - v;   // exclusive within block
    if (tid == 1023) bsum[rel * NBMAX + blockIdx.x] = sh[1023];
}

__global__ void scan_sums(const int* __restrict__ bsum, int* __restrict__ boff, int nb) {
    __shared__ int sh[NBMAX];
    int rel = blockIdx.x;
    int tid = threadIdx.x;
    int v = (tid < nb) ? bsum[rel * NBMAX + tid] : 0;
    sh[tid] = v;
    __syncthreads();
#pragma unroll
    for (int o = 1; o < NBMAX; o <<= 1) {
        int t = (tid >= o) ? sh[tid - o] : 0;
        __syncthreads();
        sh[tid] += t;
        __syncthreads();
    }
    boff[rel * NBMAX + tid] = sh[tid] - v;
}

__global__ void scan_finalize(int* __restrict__ rowptr, int* __restrict__ cursor,
                              const int* __restrict__ boff, int n) {
    int rel = blockIdx.y;
    int i = blockIdx.x * blockDim.x + threadIdx.x;
    if (i >= n) return;
    size_t idx = (size_t)rel * n + i;
    int r = rowptr[idx] + boff[rel * NBMAX + (i >> 10)];
    rowptr[idx] = r;
    cursor[idx] = r;
}

// ---------------- permute edges into dst-grouped order -----------------------
__global__ void permute_edges(const int* __restrict__ srcP, const int* __restrict__ dstP,
                              const int* __restrict__ srcS, const int* __restrict__ dstS,
                              const float* __restrict__ inv, int* __restrict__ cursor,
                              int2* __restrict__ perm, int E, int n) {
    int rel = blockIdx.y;
    const int*   src  = rel ? srcS : srcP;
    const int*   dst  = rel ? dstS : dstP;
    const float* invo = inv + (rel ? 2 * (size_t)n : 0);
    const float* invi = inv + (rel ? 3 * (size_t)n : (size_t)n);
    int e = blockIdx.x * blockDim.x + threadIdx.x;
    if (e >= E) return;
    int s = __ldg(src + e);
    int d = __ldg(dst + e);
    float c = __ldg(invo + s) * __ldg(invi + d);
    int p = atomicAdd(&cursor[(size_t)rel * n + d], 1);
    perm[(size_t)rel * EMAX + p] = make_int2(s, __float_as_int(c));
}

// ---------------- pull aggregation: acc[d] = sum coef * h[src] ---------------
// warp per dst node; no atomics, no pre-zeroing.
__global__ __launch_bounds__(256) void aggregate(
    const float* __restrict__ h, const int* __restrict__ rowptr,
    const int2* __restrict__ perm_all,
    float* __restrict__ accP, float* __restrict__ accS, int E, int n) {
    int rel = blockIdx.y;
    const int2* pm = perm_all + (size_t)rel * EMAX;
    const int*  rp = rowptr + (size_t)rel * n;
    float* acc = rel ? accS : accP;

    int warp = threadIdx.x >> 5;
    int lane = threadIdx.x & 31;
    int node = blockIdx.x * 8 + warp;
    if (node >= n) return;

    int start = __ldg(rp + node);
    int end = (node + 1 < n) ? __ldg(rp + node + 1) : E;

    float4 a = make_float4(0.f, 0.f, 0.f, 0.f);
    int j = start;
    for (; j + 1 < end; j += 2) {
        int2 p0 = __ldg(pm + j);
        int2 p1 = __ldg(pm + j + 1);
        float c0 = __int_as_float(p0.y);
        float c1 = __int_as_float(p1.y);
        float4 v0 = __ldg((const float4*)(h + (size_t)p0.x * HDIM) + lane);
        float4 v1 = __ldg((const float4*)(h + (size_t)p1.x * HDIM) + lane);
        a.x += c0 * v0.x; a.y += c0 * v0.y; a.z += c0 * v0.z; a.w += c0 * v0.w;
        a.x += c1 * v1.x; a.y += c1 * v1.y; a.z += c1 * v1.z; a.w += c1 * v1.w;
    }
    if (j < end) {
        int2 p0 = __ldg(pm + j);
        float c0 = __int_as_float(p0.y);
        float4 v0 = __ldg((const float4*)(h + (size_t)p0.x * HDIM) + lane);
        a.x += c0 * v0.x; a.y += c0 * v0.y; a.z += c0 * v0.z; a.w += c0 * v0.w;
    }
    *(float4*)(acc + (size_t)node * HDIM + lane * 4) = a;
}

// ---------------- fused dual-GEMM + mean + bias + ReLU -----------------------
#define BM 128
#define BN 128
#define BK 16
__global__ __launch_bounds__(256) void gemm_fused(
    const float* __restrict__ A0, const float* __restrict__ A1,
    const float* __restrict__ W0, const float* __restrict__ W1,
    const float* __restrict__ b0, const float* __restrict__ b1,
    float* __restrict__ out, int M) {
    __align__(16) __shared__ float As[BK][BM];
    __align__(16) __shared__ float Bs[BK][BN];

    int tid = threadIdx.x;
    int block_row = blockIdx.x * BM;
    int tx = tid & 15;
    int ty = tid >> 4;

    float acc[8][8];
#pragma unroll
    for (int i = 0; i < 8; i++)
#pragma unroll
        for (int j = 0; j < 8; j++) acc[i][j] = 0.f;

#pragma unroll
    for (int seg = 0; seg < 2; ++seg) {
        const float* A = seg ? A1 : A0;
        const float* W = seg ? W1 : W0;
        for (int kb = 0; kb < HDIM; kb += BK) {
#pragma unroll
            for (int i = 0; i < 2; ++i) {
                int idx = tid + i * 256;
                int r = idx >> 2;
                int k4 = idx & 3;
                int grow = block_row + r;
                float4 v = make_float4(0.f, 0.f, 0.f, 0.f);
                if (grow < M)
                    v = *(const float4*)(A + (size_t)grow * HDIM + kb + k4 * 4);
                As[k4 * 4 + 0][r] = v.x;
                As[k4 * 4 + 1][r] = v.y;
                As[k4 * 4 + 2][r] = v.z;
                As[k4 * 4 + 3][r] = v.w;
            }
#pragma unroll
            for (int i = 0; i < 2; ++i) {
                int idx = tid + i * 256;
                int kr = idx >> 5;
                int c4 = idx & 31;
                float4 v = *(const float4*)(W + (size_t)(kb + kr) * HDIM + c4 * 4);
                *(float4*)&Bs[kr][c4 * 4] = v;
            }
            __syncthreads();
#pragma unroll
            for (int k = 0; k < BK; ++k) {
                float a[8], b[8];
                *(float4*)&a[0] = *(const float4*)&As[k][ty * 8];
                *(float4*)&a[4] = *(const float4*)&As[k][ty * 8 + 4];
                *(float4*)&b[0] = *(const float4*)&Bs[k][tx * 8];
                *(float4*)&b[4] = *(const float4*)&Bs[k][tx * 8 + 4];
#pragma unroll
                for (int i = 0; i < 8; i++)
#pragma unroll
                    for (int j = 0; j < 8; j++) acc[i][j] += a[i] * b[j];
            }
            __syncthreads();
        }
    }

    float bsum[8];
#pragma unroll
    for (int j = 0; j < 8; j++) {
        int col = tx * 8 + j;
        bsum[j] = __ldg(b0 + col) + __ldg(b1 + col);
    }
#pragma unroll
    for (int i = 0; i < 8; i++) {
        int grow = block_row + ty * 8 + i;
        if (grow >= M) break;
        float v[8];
#pragma unroll
        for (int j = 0; j < 8; j++)
            v[j] = fmaxf(0.5f * (acc[i][j] + bsum[j]), 0.f);
        float* dst = out + (size_t)grow * HDIM + tx * 8;
        *(float4*)dst = make_float4(v[0], v[1], v[2], v[3]);
        *(float4*)(dst + 4) = make_float4(v[4], v[5], v[6], v[7]);
    }
}

// ---------------- pair classifier --------------------------------------------
__global__ __launch_bounds__(256) void pair_logits(
    const float* __restrict__ z, const int* __restrict__ ps, const int* __restrict__ pd,
    const float* __restrict__ Wc, const float* __restrict__ bc,
    float* __restrict__ out, int P) {
    __shared__ float wcT[2][256];
    int tid = threadIdx.x;
    for (int i = tid; i < 256; i += 256) {
        wcT[0][i] = __ldg(Wc + i * 2 + 0);
        wcT[1][i] = __ldg(Wc + i * 2 + 1);
    }
    __syncthreads();

    int warp = tid >> 5, lane = tid & 31;
    int pair = blockIdx.x * 8 + warp;
    if (pair >= P) return;

    int a = __ldg(ps + pair);
    int b = __ldg(pd + pair);
    float4 va = __ldg((const float4*)(z + (size_t)a * HDIM) + lane);
    float4 vb = __ldg((const float4*)(z + (size_t)b * HDIM) + lane);
    int k = lane * 4;

    float4 w0a = *(const float4*)&wcT[0][k];
    float4 w1a = *(const float4*)&wcT[1][k];
    float4 w0b = *(const float4*)&wcT[0][k + 128];
    float4 w1b = *(const float4*)&wcT[1][k + 128];

    float c0 = va.x * w0a.x + va.y * w0a.y + va.z * w0a.z + va.w * w0a.w
             + vb.x * w0b.x + vb.y * w0b.y + vb.z * w0b.z + vb.w * w0b.w;
    float c1 = va.x * w1a.x + va.y * w1a.y + va.z * w1a.z + va.w * w1a.w
             + vb.x * w1b.x + vb.y * w1b.y + vb.z * w1b.z + vb.w * w1b.w;

#pragma unroll
    for (int o = 16; o; o >>= 1) {
        c0 += __shfl_down_sync(0xFFFFFFFFu, c0, o);
        c1 += __shfl_down_sync(0xFFFFFFFFu, c1, o);
    }
    if (lane == 0) {
        out[(size_t)pair * 2 + 0] = c0 + __ldg(bc + 0);
        out[(size_t)pair * 2 + 1] = c1 + __ldg(bc + 1);
    }
}

// ---------------- launch ------------------------------------------------------
extern "C" void kernel_launch(void* const* d_in, const int* in_sizes, int n_in,
                              void* d_out, int out_size) {
    const float* feat   = (const float*)d_in[0];
    const int*   srcP   = (const int*)d_in[1];
    const int*   dstP   = (const int*)d_in[2];
    const int*   srcS   = (const int*)d_in[3];
    const int*   dstS   = (const int*)d_in[4];
    const int*   pairS  = (const int*)d_in[5];
    const int*   pairD  = (const int*)d_in[6];
    const float* W0p    = (const float*)d_in[7];
    const float* b0p    = (const float*)d_in[8];
    const float* W0s    = (const float*)d_in[9];
    const float* b0s    = (const float*)d_in[10];
    const float* W1p    = (const float*)d_in[11];
    const float* b1p    = (const float*)d_in[12];
    const float* W1s    = (const float*)d_in[13];
    const float* b1s    = (const float*)d_in[14];
    const float* Wc     = (const float*)d_in[15];
    const float* bc     = (const float*)d_in[16];

    int N = in_sizes[0] / HDIM;
    int E = in_sizes[1];
    int P = in_sizes[5];

    float* out = (float*)d_out;
    float* z = out;
    float* logits = out + (size_t)N * HDIM;

    float *h1, *accP, *accS, *deg;
    int2 *perm; int *rowptr, *cursor, *hist, *bsum, *boff;
    cudaGetSymbolAddress((void**)&h1,     g_h1);
    cudaGetSymbolAddress((void**)&accP,   g_accP);
    cudaGetSymbolAddress((void**)&accS,   g_accS);
    cudaGetSymbolAddress((void**)&deg,    g_deg);
    cudaGetSymbolAddress((void**)&perm,   g_perm);
    cudaGetSymbolAddress((void**)&rowptr, g_rowptr);
    cudaGetSymbolAddress((void**)&cursor, g_cursor);
    cudaGetSymbolAddress((void**)&hist,   g_hist);
    cudaGetSymbolAddress((void**)&bsum,   g_bsum);
    cudaGetSymbolAddress((void**)&boff,   g_boff);

    int NB = (N + 1023) / 1024;   // scan blocks per relation (<= NBMAX)

    // degrees + dst histogram
    zero_f4<<<(N + 255) / 256, 256>>>((float4*)deg, N);          // 4N floats = N float4
    zero_i<<<(2 * N + 255) / 256, 256>>>(hist, 2 * N);
    degree_kernel<<<(E + 255) / 256, 256>>>(srcP, dstP, srcS, dstS, deg, hist, E, N);
    inv_kernel<<<(4 * N + 255) / 256, 256>>>(deg, 4 * N);

    // CSR build (counting sort by dst), once per call, reused by both layers
    {
        dim3 g1(NB, 2);
        scan_partial<<<g1, 1024>>>(hist, rowptr, bsum, N);
        scan_sums<<<2, NBMAX>>>(bsum, boff, NB);
        dim3 g2((N + 255) / 256, 2);
        scan_finalize<<<g2, 256>>>(rowptr, cursor, boff, N);
        dim3 g3((E + 255) / 256, 2);
        permute_edges<<<g3, 256>>>(srcP, dstP, srcS, dstS, deg, cursor, perm, E, N);
    }

    dim3 agrid((N + 7) / 8, 2);
    int gemm_blocks = (N + BM - 1) / BM;

    // ---- layer 1 ----
    aggregate<<<agrid, 256>>>(feat, rowptr, perm, accP, accS, E, N);
    gemm_fused<<<gemm_blocks, 256>>>(accP, accS, W0p, W0s, b0p, b0s, h1, N);

    // ---- layer 2 ----
    aggregate<<<agrid, 256>>>(h1, rowptr, perm, accP, accS, E, N);
    gemm_fused<<<gemm_blocks, 256>>>(accP, accS, W1p, W1s, b1p, b1s, z, N);

    // ---- pair classifier ----
    pair_logits<<<(P + 7) / 8, 256>>>(z, pairS, pairD, Wc, bc, logits, P);
}

// round 3
// speedup vs baseline: 1.9039x; 1.0667x over previous
#include <cuda_runtime.h>
#include <cuda_fp16.h>
#include <cstdint>

#define NMAX 100000
#define EMAX 1600000
#define HDIM 128
#define NBMAX 128

// ---------------- scratch (device globals) -----------------------------------
__device__ float  g_accP[(size_t)NMAX * HDIM];
__device__ float  g_accS[(size_t)NMAX * HDIM];
__device__ __half g_h16 [(size_t)NMAX * HDIM];    // fp16 gather copy (feat16, then h1_16)
__device__ float  g_deg [(size_t)4 * NMAX];
__device__ int2   g_perm  [(size_t)2 * EMAX];
__device__ int    g_rowptr[(size_t)2 * NMAX];
__device__ int    g_cursor[(size_t)2 * NMAX];
__device__ int    g_hist  [(size_t)2 * NMAX];
__device__ int    g_bsum  [2 * NBMAX];
__device__ int    g_boff  [2 * NBMAX];

// ---------------- utility ----------------------------------------------------
__global__ void zero_f4(float4* __restrict__ p, int n4) {
    int i = blockIdx.x * blockDim.x + threadIdx.x;
    if (i < n4) p[i] = make_float4(0.f, 0.f, 0.f, 0.f);
}
__global__ void zero_i(int* __restrict__ p, int n) {
    int i = blockIdx.x * blockDim.x + threadIdx.x;
    if (i < n) p[i] = 0;
}

// feat (fp32) -> fp16, 8 elems per thread
__global__ void to_half8(const float4* __restrict__ in, uint4* __restrict__ out, int n8) {
    int i = blockIdx.x * blockDim.x + threadIdx.x;
    if (i >= n8) return;
    float4 a = __ldg(in + 2 * i);
    float4 b = __ldg(in + 2 * i + 1);
    __half2 h0 = __floats2half2_rn(a.x, a.y);
    __half2 h1 = __floats2half2_rn(a.z, a.w);
    __half2 h2 = __floats2half2_rn(b.x, b.y);
    __half2 h3 = __floats2half2_rn(b.z, b.w);
    uint4 o;
    o.x = *(uint32_t*)&h0; o.y = *(uint32_t*)&h1;
    o.z = *(uint32_t*)&h2; o.w = *(uint32_t*)&h3;
    out[i] = o;
}

__global__ void degree_kernel(const int* __restrict__ sP, const int* __restrict__ dP,
                              const int* __restrict__ sS, const int* __restrict__ dS,
                              float* __restrict__ deg, int* __restrict__ hist,
                              int E, int n) {
    int e = blockIdx.x * blockDim.x + threadIdx.x;
    if (e >= E) return;
    int dp = dP[e], ds = dS[e];
    atomicAdd(&deg[sP[e]], 1.f);
    atomicAdd(&deg[n + dp], 1.f);
    atomicAdd(&deg[2 * n + sS[e]], 1.f);
    atomicAdd(&deg[3 * n + ds], 1.f);
    atomicAdd(&hist[dp], 1);
    atomicAdd(&hist[n + ds], 1);
}

__global__ void inv_kernel(float* __restrict__ deg, int n4) {
    int i = blockIdx.x * blockDim.x + threadIdx.x;
    if (i < n4) deg[i] = rsqrtf(fmaxf(deg[i], 1.f));
}

// ---------------- exclusive scan (2-level) -----------------------------------
__global__ __launch_bounds__(1024) void scan_partial(
    const int* __restrict__ hist, int* __restrict__ rowptr,
    int* __restrict__ bsum, int n) {
    __shared__ int sh[1024];
    int rel = blockIdx.y;
    int tid = threadIdx.x;
    int i = blockIdx.x * 1024 + tid;
    int v = (i < n) ? hist[(size_t)rel * n + i] : 0;
    sh[tid] = v;
    __syncthreads();
#pragma unroll
    for (int o = 1; o < 1024; o <<= 1) {
        int t = (tid >= o) ? sh[tid - o] : 0;
        __syncthreads();
        sh[tid] += t;
        __syncthreads();
    }
    if (i < n) rowptr[(size_t)rel * n + i] = sh[tid] - v;
    if (tid == 1023) bsum[rel * NBMAX + blockIdx.x] = sh[1023];
}

__global__ void scan_sums(const int* __restrict__ bsum, int* __restrict__ boff, int nb) {
    __shared__ int sh[NBMAX];
    int rel = blockIdx.x;
    int tid = threadIdx.x;
    int v = (tid < nb) ? bsum[rel * NBMAX + tid] : 0;
    sh[tid] = v;
    __syncthreads();
#pragma unroll
    for (int o = 1; o < NBMAX; o <<= 1) {
        int t = (tid >= o) ? sh[tid - o] : 0;
        __syncthreads();
        sh[tid] += t;
        __syncthreads();
    }
    boff[rel * NBMAX + tid] = sh[tid] - v;
}

__global__ void scan_finalize(int* __restrict__ rowptr, int* __restrict__ cursor,
                              const int* __restrict__ boff, int n) {
    int rel = blockIdx.y;
    int i = blockIdx.x * blockDim.x + threadIdx.x;
    if (i >= n) return;
    size_t idx = (size_t)rel * n + i;
    int r = rowptr[idx] + boff[rel * NBMAX + (i >> 10)];
    rowptr[idx] = r;
    cursor[idx] = r;
}

__global__ void permute_edges(const int* __restrict__ srcP, const int* __restrict__ dstP,
                              const int* __restrict__ srcS, const int* __restrict__ dstS,
                              const float* __restrict__ inv, int* __restrict__ cursor,
                              int2* __restrict__ perm, int E, int n) {
    int rel = blockIdx.y;
    const int*   src  = rel ? srcS : srcP;
    const int*   dst  = rel ? dstS : dstP;
    const float* invo = inv + (rel ? 2 * (size_t)n : 0);
    const float* invi = inv + (rel ? 3 * (size_t)n : (size_t)n);
    int e = blockIdx.x * blockDim.x + threadIdx.x;
    if (e >= E) return;
    int s = __ldg(src + e);
    int d = __ldg(dst + e);
    float c = __ldg(invo + s) * __ldg(invi + d);
    int p = atomicAdd(&cursor[(size_t)rel * n + d], 1);
    perm[(size_t)rel * EMAX + p] = make_int2(s, __float_as_int(c));
}

// ---------------- pull aggregation from fp16 rows ----------------------------
// warp per dst node; lane covers 4 features (uint2 = 4 halves); fp32 accum.
__global__ __launch_bounds__(256) void aggregate_h16(
    const __half* __restrict__ h16, const int* __restrict__ rowptr,
    const int2* __restrict__ perm_all,
    float* __restrict__ accP, float* __restrict__ accS, int E, int n) {
    int rel = blockIdx.y;
    const int2* pm = perm_all + (size_t)rel * EMAX;
    const int*  rp = rowptr + (size_t)rel * n;
    float* acc = rel ? accS : accP;

    int warp = threadIdx.x >> 5;
    int lane = threadIdx.x & 31;
    int node = blockIdx.x * 8 + warp;
    if (node >= n) return;

    int start = __ldg(rp + node);
    int end = (node + 1 < n) ? __ldg(rp + node + 1) : E;

    float4 a = make_float4(0.f, 0.f, 0.f, 0.f);
    int j = start;
    for (; j + 3 < end; j += 4) {
        int2 p0 = __ldg(pm + j);
        int2 p1 = __ldg(pm + j + 1);
        int2 p2 = __ldg(pm + j + 2);
        int2 p3 = __ldg(pm + j + 3);
        uint2 v0 = __ldg((const uint2*)(h16 + (size_t)p0.x * HDIM) + lane);
        uint2 v1 = __ldg((const uint2*)(h16 + (size_t)p1.x * HDIM) + lane);
        uint2 v2 = __ldg((const uint2*)(h16 + (size_t)p2.x * HDIM) + lane);
        uint2 v3 = __ldg((const uint2*)(h16 + (size_t)p3.x * HDIM) + lane);
#define ACCUM(v, pb) { \
        float c = __int_as_float(pb.y); \
        float2 f0 = __half22float2(*(__half2*)&v.x); \
        float2 f1 = __half22float2(*(__half2*)&v.y); \
        a.x = fmaf(c, f0.x, a.x); a.y = fmaf(c, f0.y, a.y); \
        a.z = fmaf(c, f1.x, a.z); a.w = fmaf(c, f1.y, a.w); }
        ACCUM(v0, p0); ACCUM(v1, p1); ACCUM(v2, p2); ACCUM(v3, p3);
    }
    for (; j < end; ++j) {
        int2 p0 = __ldg(pm + j);
        uint2 v0 = __ldg((const uint2*)(h16 + (size_t)p0.x * HDIM) + lane);
        ACCUM(v0, p0);
    }
#undef ACCUM
    *(float4*)(acc + (size_t)node * HDIM + lane * 4) = a;
}

// ---------------- fused dual-GEMM + mean + bias + ReLU -----------------------
// out = relu(0.5*(A0@W0 + A1@W1 + b0 + b1)); writes fp32 and/or fp16.
#define BM 128
#define BN 128
#define BK 16
__global__ __launch_bounds__(256) void gemm_fused(
    const float* __restrict__ A0, const float* __restrict__ A1,
    const float* __restrict__ W0, const float* __restrict__ W1,
    const float* __restrict__ b0, const float* __restrict__ b1,
    float* __restrict__ outf, __half* __restrict__ outh, int M) {
    __align__(16) __shared__ float As[BK][BM];
    __align__(16) __shared__ float Bs[BK][BN];

    int tid = threadIdx.x;
    int block_row = blockIdx.x * BM;
    int tx = tid & 15;
    int ty = tid >> 4;

    float acc[8][8];
#pragma unroll
    for (int i = 0; i < 8; i++)
#pragma unroll
        for (int j = 0; j < 8; j++) acc[i][j] = 0.f;

#pragma unroll
    for (int seg = 0; seg < 2; ++seg) {
        const float* A = seg ? A1 : A0;
        const float* W = seg ? W1 : W0;
        for (int kb = 0; kb < HDIM; kb += BK) {
#pragma unroll
            for (int i = 0; i < 2; ++i) {
                int idx = tid + i * 256;
                int r = idx >> 2;
                int k4 = idx & 3;
                int grow = block_row + r;
                float4 v = make_float4(0.f, 0.f, 0.f, 0.f);
                if (grow < M)
                    v = *(const float4*)(A + (size_t)grow * HDIM + kb + k4 * 4);
                As[k4 * 4 + 0][r] = v.x;
                As[k4 * 4 + 1][r] = v.y;
                As[k4 * 4 + 2][r] = v.z;
                As[k4 * 4 + 3][r] = v.w;
            }
#pragma unroll
            for (int i = 0; i < 2; ++i) {
                int idx = tid + i * 256;
                int kr = idx >> 5;
                int c4 = idx & 31;
                float4 v = *(const float4*)(W + (size_t)(kb + kr) * HDIM + c4 * 4);
                *(float4*)&Bs[kr][c4 * 4] = v;
            }
            __syncthreads();
#pragma unroll
            for (int k = 0; k < BK; ++k) {
                float a[8], b[8];
                *(float4*)&a[0] = *(const float4*)&As[k][ty * 8];
                *(float4*)&a[4] = *(const float4*)&As[k][ty * 8 + 4];
                *(float4*)&b[0] = *(const float4*)&Bs[k][tx * 8];
                *(float4*)&b[4] = *(const float4*)&Bs[k][tx * 8 + 4];
#pragma unroll
                for (int i = 0; i < 8; i++)
#pragma unroll
                    for (int j = 0; j < 8; j++) acc[i][j] += a[i] * b[j];
            }
            __syncthreads();
        }
    }

    float bsum[8];
#pragma unroll
    for (int j = 0; j < 8; j++) {
        int col = tx * 8 + j;
        bsum[j] = __ldg(b0 + col) + __ldg(b1 + col);
    }
#pragma unroll
    for (int i = 0; i < 8; i++) {
        int grow = block_row + ty * 8 + i;
        if (grow >= M) break;
        float v[8];
#pragma unroll
        for (int j = 0; j < 8; j++)
            v[j] = fmaxf(0.5f * (acc[i][j] + bsum[j]), 0.f);
        if (outf) {
            float* dst = outf + (size_t)grow * HDIM + tx * 8;
            *(float4*)dst = make_float4(v[0], v[1], v[2], v[3]);
            *(float4*)(dst + 4) = make_float4(v[4], v[5], v[6], v[7]);
        }
        if (outh) {
            __half2 h0 = __floats2half2_rn(v[0], v[1]);
            __half2 h1 = __floats2half2_rn(v[2], v[3]);
            __half2 h2 = __floats2half2_rn(v[4], v[5]);
            __half2 h3 = __floats2half2_rn(v[6], v[7]);
            uint4 o;
            o.x = *(uint32_t*)&h0; o.y = *(uint32_t*)&h1;
            o.z = *(uint32_t*)&h2; o.w = *(uint32_t*)&h3;
            *(uint4*)(outh + (size_t)grow * HDIM + tx * 8) = o;
        }
    }
}

// ---------------- pair classifier --------------------------------------------
__global__ __launch_bounds__(256) void pair_logits(
    const float* __restrict__ z, const int* __restrict__ ps, const int* __restrict__ pd,
    const float* __restrict__ Wc, const float* __restrict__ bc,
    float* __restrict__ out, int P) {
    __shared__ float wcT[2][256];
    int tid = threadIdx.x;
    for (int i = tid; i < 256; i += 256) {
        wcT[0][i] = __ldg(Wc + i * 2 + 0);
        wcT[1][i] = __ldg(Wc + i * 2 + 1);
    }
    __syncthreads();

    int warp = tid >> 5, lane = tid & 31;
    int pair = blockIdx.x * 8 + warp;
    if (pair >= P) return;

    int a = __ldg(ps + pair);
    int b = __ldg(pd + pair);
    float4 va = __ldg((const float4*)(z + (size_t)a * HDIM) + lane);
    float4 vb = __ldg((const float4*)(z + (size_t)b * HDIM) + lane);
    int k = lane * 4;

    float4 w0a = *(const float4*)&wcT[0][k];
    float4 w1a = *(const float4*)&wcT[1][k];
    float4 w0b = *(const float4*)&wcT[0][k + 128];
    float4 w1b = *(const float4*)&wcT[1][k + 128];

    float c0 = va.x * w0a.x + va.y * w0a.y + va.z * w0a.z + va.w * w0a.w
             + vb.x * w0b.x + vb.y * w0b.y + vb.z * w0b.z + vb.w * w0b.w;
    float c1 = va.x * w1a.x + va.y * w1a.y + va.z * w1a.z + va.w * w1a.w
             + vb.x * w1b.x + vb.y * w1b.y + vb.z * w1b.z + vb.w * w1b.w;

#pragma unroll
    for (int o = 16; o; o >>= 1) {
        c0 += __shfl_down_sync(0xFFFFFFFFu, c0, o);
        c1 += __shfl_down_sync(0xFFFFFFFFu, c1, o);
    }
    if (lane == 0) {
        out[(size_t)pair * 2 + 0] = c0 + __ldg(bc + 0);
        out[(size_t)pair * 2 + 1] = c1 + __ldg(bc + 1);
    }
}

// ---------------- launch ------------------------------------------------------
extern "C" void kernel_launch(void* const* d_in, const int* in_sizes, int n_in,
                              void* d_out, int out_size) {
    const float* feat   = (const float*)d_in[0];
    const int*   srcP   = (const int*)d_in[1];
    const int*   dstP   = (const int*)d_in[2];
    const int*   srcS   = (const int*)d_in[3];
    const int*   dstS   = (const int*)d_in[4];
    const int*   pairS  = (const int*)d_in[5];
    const int*   pairD  = (const int*)d_in[6];
    const float* W0p    = (const float*)d_in[7];
    const float* b0p    = (const float*)d_in[8];
    const float* W0s    = (const float*)d_in[9];
    const float* b0s    = (const float*)d_in[10];
    const float* W1p    = (const float*)d_in[11];
    const float* b1p    = (const float*)d_in[12];
    const float* W1s    = (const float*)d_in[13];
    const float* b1s    = (const float*)d_in[14];
    const float* Wc     = (const float*)d_in[15];
    const float* bc     = (const float*)d_in[16];

    int N = in_sizes[0] / HDIM;
    int E = in_sizes[1];
    int P = in_sizes[5];

    float* out = (float*)d_out;
    float* z = out;
    float* logits = out + (size_t)N * HDIM;

    float *accP, *accS, *deg;
    __half* h16;
    int2 *perm; int *rowptr, *cursor, *hist, *bsum, *boff;
    cudaGetSymbolAddress((void**)&accP,   g_accP);
    cudaGetSymbolAddress((void**)&accS,   g_accS);
    cudaGetSymbolAddress((void**)&h16,    g_h16);
    cudaGetSymbolAddress((void**)&deg,    g_deg);
    cudaGetSymbolAddress((void**)&perm,   g_perm);
    cudaGetSymbolAddress((void**)&rowptr, g_rowptr);
    cudaGetSymbolAddress((void**)&cursor, g_cursor);
    cudaGetSymbolAddress((void**)&hist,   g_hist);
    cudaGetSymbolAddress((void**)&bsum,   g_bsum);
    cudaGetSymbolAddress((void**)&boff,   g_boff);

    int NB = (N + 1023) / 1024;

    // degrees + histogram + feat->fp16 (independent, back-to-back)
    zero_f4<<<(N + 255) / 256, 256>>>((float4*)deg, N);
    zero_i<<<(2 * N + 255) / 256, 256>>>(hist, 2 * N);
    degree_kernel<<<(E + 255) / 256, 256>>>(srcP, dstP, srcS, dstS, deg, hist, E, N);
    inv_kernel<<<(4 * N + 255) / 256, 256>>>(deg, 4 * N);
    {
        int n8 = (N * HDIM) / 8;
        to_half8<<<(n8 + 255) / 256, 256>>>((const float4*)feat, (uint4*)h16, n8);
    }

    // CSR build (counting sort by dst)
    {
        dim3 g1(NB, 2);
        scan_partial<<<g1, 1024>>>(hist, rowptr, bsum, N);
        scan_sums<<<2, NBMAX>>>(bsum, boff, NB);
        dim3 g2((N + 255) / 256, 2);
        scan_finalize<<<g2, 256>>>(rowptr, cursor, boff, N);
        dim3 g3((E + 255) / 256, 2);
        permute_edges<<<g3, 256>>>(srcP, dstP, srcS, dstS, deg, cursor, perm, E, N);
    }

    dim3 agrid((N + 7) / 8, 2);
    int gemm_blocks = (N + BM - 1) / BM;

    // ---- layer 1 ---- (aggregate fp16 feat; GEMM emits fp16 h1 only)
    aggregate_h16<<<agrid, 256>>>(h16, rowptr, perm, accP, accS, E, N);
    gemm_fused<<<gemm_blocks, 256>>>(accP, accS, W0p, W0s, b0p, b0s,
                                     (float*)nullptr, h16, N);

    // ---- layer 2 ---- (aggregate fp16 h1; GEMM emits fp32 z)
    aggregate_h16<<<agrid, 256>>>(h16, rowptr, perm, accP, accS, E, N);
    gemm_fused<<<gemm_blocks, 256>>>(accP, accS, W1p, W1s, b1p, b1s,
                                     z, (__half*)nullptr, N);

    // ---- pair classifier ----
    pair_logits<<<(P + 7) / 8, 256>>>(z, pairS, pairD, Wc, bc, logits, P);
}

// round 5
// speedup vs baseline: 2.9194x; 1.5333x over previous
#include <cuda_runtime.h>
#include <cuda_fp16.h>
#include <cstdint>

#define NMAX 100000
#define EMAX 1600000
#define HDIM 128
#define NBMAX 128

// ---------------- scratch (device globals) -----------------------------------
__device__ __half g_accP[(size_t)NMAX * HDIM];
__device__ __half g_accS[(size_t)NMAX * HDIM];
__device__ __half g_h16 [(size_t)NMAX * HDIM];    // fp16 gather copy (feat16, then h1_16)
__device__ __half g_wt0 [(size_t)HDIM * 2 * HDIM]; // WT[n][k] layer0 (k: [W0p;W0s])
__device__ __half g_wt1 [(size_t)HDIM * 2 * HDIM];
__device__ float  g_deg [(size_t)4 * NMAX];
__device__ int2   g_perm  [(size_t)2 * EMAX];
__device__ int    g_rowptr[(size_t)2 * NMAX];
__device__ int    g_cursor[(size_t)2 * NMAX];
__device__ int    g_hist  [(size_t)2 * NMAX];
__device__ int    g_bsum  [2 * NBMAX];
__device__ int    g_boff  [2 * NBMAX];

// ---------------- utility ----------------------------------------------------
__global__ void zero_f4(float4* __restrict__ p, int n4) {
    int i = blockIdx.x * blockDim.x + threadIdx.x;
    if (i < n4) p[i] = make_float4(0.f, 0.f, 0.f, 0.f);
}
__global__ void zero_i(int* __restrict__ p, int n) {
    int i = blockIdx.x * blockDim.x + threadIdx.x;
    if (i < n) p[i] = 0;
}

__global__ void to_half8(const float4* __restrict__ in, uint4* __restrict__ out, int n8) {
    int i = blockIdx.x * blockDim.x + threadIdx.x;
    if (i >= n8) return;
    float4 a = __ldg(in + 2 * i);
    float4 b = __ldg(in + 2 * i + 1);
    __half2 h0 = __floats2half2_rn(a.x, a.y);
    __half2 h1 = __floats2half2_rn(a.z, a.w);
    __half2 h2 = __floats2half2_rn(b.x, b.y);
    __half2 h3 = __floats2half2_rn(b.z, b.w);
    uint4 o;
    o.x = *(uint32_t*)&h0; o.y = *(uint32_t*)&h1;
    o.z = *(uint32_t*)&h2; o.w = *(uint32_t*)&h3;
    out[i] = o;
}

// WT[n][k] fp16 : k<128 -> Wp[k][n], k>=128 -> Ws[k-128][n]
__global__ void make_wt(const float* __restrict__ Wp, const float* __restrict__ Ws,
                        __half* __restrict__ wt) {
    int n = blockIdx.x;        // 0..127
    int k = threadIdx.x;       // 0..255
    float v = (k < HDIM) ? __ldg(Wp + (size_t)k * HDIM + n)
                         : __ldg(Ws + (size_t)(k - HDIM) * HDIM + n);
    wt[(size_t)n * 2 * HDIM + k] = __float2half(v);
}

__global__ void degree_kernel(const int* __restrict__ sP, const int* __restrict__ dP,
                              const int* __restrict__ sS, const int* __restrict__ dS,
                              float* __restrict__ deg, int* __restrict__ hist,
                              int E, int n) {
    int e = blockIdx.x * blockDim.x + threadIdx.x;
    if (e >= E) return;
    int dp = dP[e], ds = dS[e];
    atomicAdd(&deg[sP[e]], 1.f);
    atomicAdd(&deg[n + dp], 1.f);
    atomicAdd(&deg[2 * n + sS[e]], 1.f);
    atomicAdd(&deg[3 * n + ds], 1.f);
    atomicAdd(&hist[dp], 1);
    atomicAdd(&hist[n + ds], 1);
}

__global__ void inv_kernel(float* __restrict__ deg, int n4) {
    int i = blockIdx.x * blockDim.x + threadIdx.x;
    if (i < n4) deg[i] = rsqrtf(fmaxf(deg[i], 1.f));
}

// ---------------- exclusive scan (2-level) -----------------------------------
__global__ __launch_bounds__(1024) void scan_partial(
    const int* __restrict__ hist, int* __restrict__ rowptr,
    int* __restrict__ bsum, int n) {
    __shared__ int sh[1024];
    int rel = blockIdx.y;
    int tid = threadIdx.x;
    int i = blockIdx.x * 1024 + tid;
    int v = (i < n) ? hist[(size_t)rel * n + i] : 0;
    sh[tid] = v;
    __syncthreads();
#pragma unroll
    for (int o = 1; o < 1024; o <<= 1) {
        int t = (tid >= o) ? sh[tid - o] : 0;
        __syncthreads();
        sh[tid] += t;
        __syncthreads();
    }
    if (i < n) rowptr[(size_t)rel * n + i] = sh[tid] - v;
    if (tid == 1023) bsum[rel * NBMAX + blockIdx.x] = sh[1023];
}

__global__ void scan_sums(const int* __restrict__ bsum, int* __restrict__ boff, int nb) {
    __shared__ int sh[NBMAX];
    int rel = blockIdx.x;
    int tid = threadIdx.x;
    int v = (tid < nb) ? bsum[rel * NBMAX + tid] : 0;
    sh[tid] = v;
    __syncthreads();
#pragma unroll
    for (int o = 1; o < NBMAX; o <<= 1) {
        int t = (tid >= o) ? sh[tid - o] : 0;
        __syncthreads();
        sh[tid] += t;
        __syncthreads();
    }
    boff[rel * NBMAX + tid] = sh[tid] - v;
}

__global__ void scan_finalize(int* __restrict__ rowptr, int* __restrict__ cursor,
                              const int* __restrict__ boff, int n) {
    int rel = blockIdx.y;
    int i = blockIdx.x * blockDim.x + threadIdx.x;
    if (i >= n) return;
    size_t idx = (size_t)rel * n + i;
    int r = rowptr[idx] + boff[rel * NBMAX + (i >> 10)];
    rowptr[idx] = r;
    cursor[idx] = r;
}

__global__ void permute_edges(const int* __restrict__ srcP, const int* __restrict__ dstP,
                              const int* __restrict__ srcS, const int* __restrict__ dstS,
                              const float* __restrict__ inv, int* __restrict__ cursor,
                              int2* __restrict__ perm, int E, int n) {
    int rel = blockIdx.y;
    const int*   src  = rel ? srcS : srcP;
    const int*   dst  = rel ? dstS : dstP;
    const float* invo = inv + (rel ? 2 * (size_t)n : 0);
    const float* invi = inv + (rel ? 3 * (size_t)n : (size_t)n);
    int e = blockIdx.x * blockDim.x + threadIdx.x;
    if (e >= E) return;
    int s = __ldg(src + e);
    int d = __ldg(dst + e);
    float c = __ldg(invo + s) * __ldg(invi + d);
    int p = atomicAdd(&cursor[(size_t)rel * n + d], 1);
    perm[(size_t)rel * EMAX + p] = make_int2(s, __float_as_int(c));
}

// ---------------- pull aggregation: fp16 in, fp32 accum, fp16 out ------------
__global__ __launch_bounds__(256) void aggregate_h16(
    const __half* __restrict__ h16, const int* __restrict__ rowptr,
    const int2* __restrict__ perm_all,
    __half* __restrict__ accP, __half* __restrict__ accS, int E, int n) {
    int rel = blockIdx.y;
    const int2* pm = perm_all + (size_t)rel * EMAX;
    const int*  rp = rowptr + (size_t)rel * n;
    __half* acc = rel ? accS : accP;

    int warp = threadIdx.x >> 5;
    int lane = threadIdx.x & 31;
    int node = blockIdx.x * 8 + warp;
    if (node >= n) return;

    int start = __ldg(rp + node);
    int end = (node + 1 < n) ? __ldg(rp + node + 1) : E;

    float4 a = make_float4(0.f, 0.f, 0.f, 0.f);
    int j = start;
    for (; j + 3 < end; j += 4) {
        int2 p0 = __ldg(pm + j);
        int2 p1 = __ldg(pm + j + 1);
        int2 p2 = __ldg(pm + j + 2);
        int2 p3 = __ldg(pm + j + 3);
        uint2 v0 = __ldg((const uint2*)(h16 + (size_t)p0.x * HDIM) + lane);
        uint2 v1 = __ldg((const uint2*)(h16 + (size_t)p1.x * HDIM) + lane);
        uint2 v2 = __ldg((const uint2*)(h16 + (size_t)p2.x * HDIM) + lane);
        uint2 v3 = __ldg((const uint2*)(h16 + (size_t)p3.x * HDIM) + lane);
#define ACCUM(v, pb) { \
        float c = __int_as_float(pb.y); \
        float2 f0 = __half22float2(*(__half2*)&v.x); \
        float2 f1 = __half22float2(*(__half2*)&v.y); \
        a.x = fmaf(c, f0.x, a.x); a.y = fmaf(c, f0.y, a.y); \
        a.z = fmaf(c, f1.x, a.z); a.w = fmaf(c, f1.y, a.w); }
        ACCUM(v0, p0); ACCUM(v1, p1); ACCUM(v2, p2); ACCUM(v3, p3);
    }
    for (; j < end; ++j) {
        int2 p0 = __ldg(pm + j);
        uint2 v0 = __ldg((const uint2*)(h16 + (size_t)p0.x * HDIM) + lane);
        ACCUM(v0, p0);
    }
#undef ACCUM
    __half2 o0 = __floats2half2_rn(a.x, a.y);
    __half2 o1 = __floats2half2_rn(a.z, a.w);
    uint2 st; st.x = *(uint32_t*)&o0; st.y = *(uint32_t*)&o1;
    *(uint2*)(acc + (size_t)node * HDIM + lane * 4) = st;
}

// ---------------- tensor-core fused dual-GEMM --------------------------------
// out = relu(0.5*(A@WT^T + b0 + b1)) where A=[accP|accS] fp16 [M,256],
// WT fp16 [128 n][256 k]. mma.sync.m16n8k16, fp32 accum.
#define PADK 264                       // 256 + 8 halves padding
#define GEMM_SMEM (2 * 128 * PADK * 2) // A + WT tiles, bytes = 135168

__global__ __launch_bounds__(256) void gemm_tc(
    const __half* __restrict__ A0, const __half* __restrict__ A1,
    const __half* __restrict__ wt,
    const float* __restrict__ b0, const float* __restrict__ b1,
    float* __restrict__ outf, __half* __restrict__ outh, int M) {
    extern __shared__ __half sm[];
    __half* Asm = sm;                 // [128][PADK]
    __half* Bsm = sm + 128 * PADK;    // [128][PADK]

    int tid = threadIdx.x;
    int brow = blockIdx.x * 128;

    // load A block: 2 segs x 128 rows x 128 halves
#pragma unroll
    for (int seg = 0; seg < 2; ++seg) {
        const __half* src = seg ? A1 : A0;
#pragma unroll
        for (int i = 0; i < 8; ++i) {
            int idx = tid + i * 256;      // 0..2047
            int r = idx >> 4;
            int u = idx & 15;
            int grow = brow + r;
            uint4 v = make_uint4(0u, 0u, 0u, 0u);
            if (grow < M) v = *(const uint4*)(src + (size_t)grow * HDIM + u * 8);
            *(uint4*)(Asm + r * PADK + seg * HDIM + u * 8) = v;
        }
    }
    // load WT: 128 rows x 256 halves
#pragma unroll
    for (int i = 0; i < 16; ++i) {
        int idx = tid + i * 256;          // 0..4095
        int nr = idx >> 5;
        int u = idx & 31;
        *(uint4*)(Bsm + nr * PADK + u * 8) = *(const uint4*)(wt + (size_t)nr * 256 + u * 8);
    }
    __syncthreads();

    int warp = tid >> 5;
    int lane = tid & 31;
    int g = lane >> 2;       // 0..7
    int tig = lane & 3;      // 0..3

    const __half* Aw = Asm + warp * 16 * PADK;
    float c[16][4];
#pragma unroll
    for (int nb = 0; nb < 16; ++nb)
#pragma unroll
        for (int q = 0; q < 4; ++q) c[nb][q] = 0.f;

#pragma unroll
    for (int kc = 0; kc < 16; ++kc) {
        uint32_t a0 = *(const uint32_t*)(Aw + g * PADK + kc * 16 + tig * 2);
        uint32_t a1 = *(const uint32_t*)(Aw + (g + 8) * PADK + kc * 16 + tig * 2);
        uint32_t a2 = *(const uint32_t*)(Aw + g * PADK + kc * 16 + 8 + tig * 2);
        uint32_t a3 = *(const uint32_t*)(Aw + (g + 8) * PADK + kc * 16 + 8 + tig * 2);
#pragma unroll
        for (int nb = 0; nb < 16; ++nb) {
            const __half* Bb = Bsm + (nb * 8 + g) * PADK + kc * 16 + tig * 2;
            uint32_t bb0 = *(const uint32_t*)(Bb);
            uint32_t bb1 = *(const uint32_t*)(Bb + 8);
            asm volatile(
                "mma.sync.aligned.m16n8k16.row.col.f32.f16.f16.f32 "
                "{%0,%1,%2,%3}, {%4,%5,%6,%7}, {%8,%9}, {%0,%1,%2,%3};"
                : "+f"(c[nb][0]), "+f"(c[nb][1]), "+f"(c[nb][2]), "+f"(c[nb][3])
                : "r"(a0), "r"(a1), "r"(a2), "r"(a3), "r"(bb0), "r"(bb1));
        }
    }

    // epilogue
    int row0 = brow + warp * 16 + g;
    int row1 = row0 + 8;
#pragma unroll
    for (int nb = 0; nb < 16; ++nb) {
        int n0 = nb * 8 + tig * 2;
        float bias0 = __ldg(b0 + n0) + __ldg(b1 + n0);
        float bias1 = __ldg(b0 + n0 + 1) + __ldg(b1 + n0 + 1);
        float v00 = fmaxf(0.5f * (c[nb][0] + bias0), 0.f);
        float v01 = fmaxf(0.5f * (c[nb][1] + bias1), 0.f);
        float v10 = fmaxf(0.5f * (c[nb][2] + bias0), 0.f);
        float v11 = fmaxf(0.5f * (c[nb][3] + bias1), 0.f);
        if (outf) {
            if (row0 < M) *(float2*)(outf + (size_t)row0 * HDIM + n0) = make_float2(v00, v01);
            if (row1 < M) *(float2*)(outf + (size_t)row1 * HDIM + n0) = make_float2(v10, v11);
        }
        if (outh) {
            if (row0 < M) {
                __half2 h = __floats2half2_rn(v00, v01);
                *(__half2*)(outh + (size_t)row0 * HDIM + n0) = h;
            }
            if (row1 < M) {
                __half2 h = __floats2half2_rn(v10, v11);
                *(__half2*)(outh + (size_t)row1 * HDIM + n0) = h;
            }
        }
    }
}

// ---------------- pair classifier --------------------------------------------
__global__ __launch_bounds__(256) void pair_logits(
    const float* __restrict__ z, const int* __restrict__ ps, const int* __restrict__ pd,
    const float* __restrict__ Wc, const float* __restrict__ bc,
    float* __restrict__ out, int P) {
    __shared__ float wcT[2][256];
    int tid = threadIdx.x;
    for (int i = tid; i < 256; i += 256) {
        wcT[0][i] = __ldg(Wc + i * 2 + 0);
        wcT[1][i] = __ldg(Wc + i * 2 + 1);
    }
    __syncthreads();

    int warp = tid >> 5, lane = tid & 31;
    int pair = blockIdx.x * 8 + warp;
    if (pair >= P) return;

    int a = __ldg(ps + pair);
    int b = __ldg(pd + pair);
    float4 va = __ldg((const float4*)(z + (size_t)a * HDIM) + lane);
    float4 vb = __ldg((const float4*)(z + (size_t)b * HDIM) + lane);
    int k = lane * 4;

    float4 w0a = *(const float4*)&wcT[0][k];
    float4 w1a = *(const float4*)&wcT[1][k];
    float4 w0b = *(const float4*)&wcT[0][k + 128];
    float4 w1b = *(const float4*)&wcT[1][k + 128];

    float c0 = va.x * w0a.x + va.y * w0a.y + va.z * w0a.z + va.w * w0a.w
             + vb.x * w0b.x + vb.y * w0b.y + vb.z * w0b.z + vb.w * w0b.w;
    float c1 = va.x * w1a.x + va.y * w1a.y + va.z * w1a.z + va.w * w1a.w
             + vb.x * w1b.x + vb.y * w1b.y + vb.z * w1b.z + vb.w * w1b.w;

#pragma unroll
    for (int o = 16; o; o >>= 1) {
        c0 += __shfl_down_sync(0xFFFFFFFFu, c0, o);
        c1 += __shfl_down_sync(0xFFFFFFFFu, c1, o);
    }
    if (lane == 0) {
        out[(size_t)pair * 2 + 0] = c0 + __ldg(bc + 0);
        out[(size_t)pair * 2 + 1] = c1 + __ldg(bc + 1);
    }
}

// ---------------- launch ------------------------------------------------------
extern "C" void kernel_launch(void* const* d_in, const int* in_sizes, int n_in,
                              void* d_out, int out_size) {
    const float* feat   = (const float*)d_in[0];
    const int*   srcP   = (const int*)d_in[1];
    const int*   dstP   = (const int*)d_in[2];
    const int*   srcS   = (const int*)d_in[3];
    const int*   dstS   = (const int*)d_in[4];
    const int*   pairS  = (const int*)d_in[5];
    const int*   pairD  = (const int*)d_in[6];
    const float* W0p    = (const float*)d_in[7];
    const float* b0p    = (const float*)d_in[8];
    const float* W0s    = (const float*)d_in[9];
    const float* b0s    = (const float*)d_in[10];
    const float* W1p    = (const float*)d_in[11];
    const float* b1p    = (const float*)d_in[12];
    const float* W1s    = (const float*)d_in[13];
    const float* b1s    = (const float*)d_in[14];
    const float* Wc     = (const float*)d_in[15];
    const float* bc     = (const float*)d_in[16];

    int N = in_sizes[0] / HDIM;
    int E = in_sizes[1];
    int P = in_sizes[5];

    float* out = (float*)d_out;
    float* z = out;
    float* logits = out + (size_t)N * HDIM;

    __half *accP, *accS, *h16, *wt0, *wt1;
    float *deg;
    int2 *perm; int *rowptr, *cursor, *hist, *bsum, *boff;
    cudaGetSymbolAddress((void**)&accP,   g_accP);
    cudaGetSymbolAddress((void**)&accS,   g_accS);
    cudaGetSymbolAddress((void**)&h16,    g_h16);
    cudaGetSymbolAddress((void**)&wt0,    g_wt0);
    cudaGetSymbolAddress((void**)&wt1,    g_wt1);
    cudaGetSymbolAddress((void**)&deg,    g_deg);
    cudaGetSymbolAddress((void**)&perm,   g_perm);
    cudaGetSymbolAddress((void**)&rowptr, g_rowptr);
    cudaGetSymbolAddress((void**)&cursor, g_cursor);
    cudaGetSymbolAddress((void**)&hist,   g_hist);
    cudaGetSymbolAddress((void**)&bsum,   g_bsum);
    cudaGetSymbolAddress((void**)&boff,   g_boff);

    // unconditional, idempotent (no static guards allowed)
    cudaFuncSetAttribute(gemm_tc, cudaFuncAttributeMaxDynamicSharedMemorySize,
                         GEMM_SMEM);

    int NB = (N + 1023) / 1024;

    // degrees + histogram + conversions (independent)
    zero_f4<<<(N + 255) / 256, 256>>>((float4*)deg, N);
    zero_i<<<(2 * N + 255) / 256, 256>>>(hist, 2 * N);
    degree_kernel<<<(E + 255) / 256, 256>>>(srcP, dstP, srcS, dstS, deg, hist, E, N);
    inv_kernel<<<(4 * N + 255) / 256, 256>>>(deg, 4 * N);
    {
        int n8 = (N * HDIM) / 8;
        to_half8<<<(n8 + 255) / 256, 256>>>((const float4*)feat, (uint4*)h16, n8);
    }
    make_wt<<<HDIM, 2 * HDIM>>>(W0p, W0s, wt0);
    make_wt<<<HDIM, 2 * HDIM>>>(W1p, W1s, wt1);

    // CSR build (counting sort by dst)
    {
        dim3 g1(NB, 2);
        scan_partial<<<g1, 1024>>>(hist, rowptr, bsum, N);
        scan_sums<<<2, NBMAX>>>(bsum, boff, NB);
        dim3 g2((N + 255) / 256, 2);
        scan_finalize<<<g2, 256>>>(rowptr, cursor, boff, N);
        dim3 g3((E + 255) / 256, 2);
        permute_edges<<<g3, 256>>>(srcP, dstP, srcS, dstS, deg, cursor, perm, E, N);
    }

    dim3 agrid((N + 7) / 8, 2);
    int gemm_blocks = (N + 127) / 128;

    // ---- layer 1 ----
    aggregate_h16<<<agrid, 256>>>(h16, rowptr, perm, accP, accS, E, N);
    gemm_tc<<<gemm_blocks, 256, GEMM_SMEM>>>(accP, accS, wt0, b0p, b0s,
                                             (float*)nullptr, h16, N);

    // ---- layer 2 ----
    aggregate_h16<<<agrid, 256>>>(h16, rowptr, perm, accP, accS, E, N);
    gemm_tc<<<gemm_blocks, 256, GEMM_SMEM>>>(accP, accS, wt1, b1p, b1s,
                                             z, (__half*)nullptr, N);

    // ---- pair classifier ----
    pair_logits<<<(P + 7) / 8, 256>>>(z, pairS, pairD, Wc, bc, logits, P);
}